// round 1
// baseline (speedup 1.0000x reference)
#include <cuda_runtime.h>

// Problem constants (fixed by setup_inputs: n=4, c=16, h=w=64, patch=3)
#define NB 4
#define CH 16
#define HW 4096          // 64*64
#define KD 144           // c * patch*patch
#define TM 128           // query tile
#define TN 128           // target tile
#define KC 16            // K chunk

// Scratch (allocation-free: __device__ globals)
__device__ float g_Qd[NB * KD * HW];   // [b][k][pix], K-major descriptors of s
__device__ float g_Pd[NB * KD * HW];   // [b][k][pix], K-major descriptors of t
__device__ float g_qn[NB * HW];
__device__ float g_pn[NB * HW];

// ---------------------------------------------------------------------------
// Prep: build patch descriptors (replicate-pad shifts) + squared norms.
// blockIdx.y == 0 -> s/Q, == 1 -> t/P
// ---------------------------------------------------------------------------
__global__ void prep_kernel(const float* __restrict__ s, const float* __restrict__ t) {
    int idx = blockIdx.x * blockDim.x + threadIdx.x;
    if (idx >= NB * HW) return;
    const float* src = blockIdx.y ? t : s;
    float* dst = blockIdx.y ? g_Pd : g_Qd;
    float* nrm = blockIdx.y ? g_pn : g_qn;

    int b = idx >> 12;
    int pix = idx & (HW - 1);
    int iy = pix >> 6, ix = pix & 63;

    float acc = 0.f;
    for (int c = 0; c < CH; c++) {
        const float* sc = src + ((size_t)(b * CH + c) << 12);
#pragma unroll
        for (int dy = 0; dy < 3; dy++) {
            int y = iy + dy - 1; y = y < 0 ? 0 : (y > 63 ? 63 : y);
#pragma unroll
            for (int dx = 0; dx < 3; dx++) {
                int x = ix + dx - 1; x = x < 0 ? 0 : (x > 63 ? 63 : x);
                float v = sc[(y << 6) + x];
                dst[(size_t)(b * KD + c * 9 + dy * 3 + dx) * HW + pix] = v;
                acc = fmaf(v, v, acc);
            }
        }
    }
    nrm[idx] = acc;
}

// ---------------------------------------------------------------------------
// Fused GEMM + row-argmin.
// Grid: (HW/TM, NB). Block: 256 threads, 8x8 micro-tile.
// Q block (KD x TM) fully resident in smem; P streamed in KC chunks.
// d2 = (qn - 2*cross) + pn, running min per query, lowest-index tie-break.
// ---------------------------------------------------------------------------
__global__ __launch_bounds__(256, 1) void nn_kernel(float* __restrict__ out) {
    extern __shared__ float smem[];
    float* Qs  = smem;                    // [KD][TM] = 18432 floats
    float* Ps  = smem + KD * TM;          // [KC][TN] = 2048 floats
    float* qns = Ps + KC * TN;            // [TM]
    float* pns = qns + TM;                // [TN]

    int b   = blockIdx.y;
    int q0  = blockIdx.x * TM;
    int tid = threadIdx.x;
    int tx  = tid & 15;          // target micro-col group
    int ty  = tid >> 4;          // query micro-row group

    // Load entire Q block (coalesced: contiguous in pixel index)
    const float* Qg = g_Qd + (size_t)b * KD * HW + q0;
#pragma unroll
    for (int r = 0; r < (KD * TM) / 256; r++) {
        int e = tid + r * 256;
        Qs[e] = Qg[(size_t)(e >> 7) * HW + (e & 127)];
    }
    if (tid < TM) qns[tid] = g_qn[b * HW + q0 + tid];
    __syncthreads();

    float bestd[8];
    int   bestj[8];
#pragma unroll
    for (int m = 0; m < 8; m++) { bestd[m] = 3.4e38f; bestj[m] = 0; }

    const float* Pg = g_Pd + (size_t)b * KD * HW;

    for (int j0 = 0; j0 < HW; j0 += TN) {
        float acc[8][8];
#pragma unroll
        for (int m = 0; m < 8; m++)
#pragma unroll
            for (int n = 0; n < 8; n++) acc[m][n] = 0.f;

        for (int kc = 0; kc < KD; kc += KC) {
            // Stage P chunk (KC x TN), coalesced
#pragma unroll
            for (int r = 0; r < (KC * TN) / 256; r++) {
                int e = tid + r * 256;
                Ps[e] = Pg[(size_t)(kc + (e >> 7)) * HW + j0 + (e & 127)];
            }
            if (kc == 0 && tid < TN) pns[tid] = g_pn[b * HW + j0 + tid];
            __syncthreads();

#pragma unroll
            for (int k = 0; k < KC; k++) {
                float a[8], bb[8];
#pragma unroll
                for (int m = 0; m < 8; m++) a[m]  = Qs[(kc + k) * TM + ty + 16 * m];
#pragma unroll
                for (int n = 0; n < 8; n++) bb[n] = Ps[k * TN + tx + 16 * n];
#pragma unroll
                for (int m = 0; m < 8; m++)
#pragma unroll
                    for (int n = 0; n < 8; n++)
                        acc[m][n] = fmaf(a[m], bb[n], acc[m][n]);
            }
            __syncthreads();
        }

        // Epilogue: d2 = (qn - 2*cross) + pn, running min (ascending j keeps
        // first occurrence under strict <)
#pragma unroll
        for (int m = 0; m < 8; m++) {
            float qni = qns[ty + 16 * m];
#pragma unroll
            for (int n = 0; n < 8; n++) {
                int jl = tx + 16 * n;
                float d = fmaf(-2.f, acc[m][n], qni) + pns[jl];
                if (d < bestd[m]) { bestd[m] = d; bestj[m] = j0 + jl; }
            }
        }
    }

    // Cross-thread reduce over the 16 column groups sharing each query row.
    __syncthreads();
    float* rd = smem;                       // [TM][16]
    int*   rj = (int*)(smem + TM * 16);     // [TM][16]
#pragma unroll
    for (int m = 0; m < 8; m++) {
        int i = ty + 16 * m;
        rd[i * 16 + tx] = bestd[m];
        rj[i * 16 + tx] = bestj[m];
    }
    __syncthreads();

    if (tid < TM) {
        float bd = rd[tid * 16];
        int   bj = rj[tid * 16];
#pragma unroll
        for (int x = 1; x < 16; x++) {
            float d = rd[tid * 16 + x];
            int   j = rj[tid * 16 + x];
            if (d < bd || (d == bd && j < bj)) { bd = d; bj = j; }
        }
        int pix = q0 + tid;
        // Output layout: nnf (n,2,h,w) as floats, then nnd (n,1,h,w)
        out[(size_t)b * 2 * HW + pix]          = (float)(bj >> 6);   // row index
        out[(size_t)b * 2 * HW + HW + pix]     = (float)(bj & 63);   // col index
        out[(size_t)NB * 2 * HW + (size_t)b * HW + pix] = bd;        // nnd
    }
}

extern "C" void kernel_launch(void* const* d_in, const int* in_sizes, int n_in,
                              void* d_out, int out_size) {
    const float* s = (const float*)d_in[0];
    const float* t = (const float*)d_in[1];
    float* out = (float*)d_out;

    const int smem_bytes = (KD * TM + KC * TN + TM + TN) * 4;  // 82944
    cudaFuncSetAttribute(nn_kernel, cudaFuncAttributeMaxDynamicSharedMemorySize,
                         smem_bytes);

    prep_kernel<<<dim3((NB * HW + 255) / 256, 2), 256>>>(s, t);
    nn_kernel<<<dim3(HW / TM, NB), 256, smem_bytes>>>(out);
}

// round 2
// speedup vs baseline: 1.5248x; 1.5248x over previous
#include <cuda_runtime.h>

// Fixed problem: n=4, c=16, h=w=64, patch=3
#define NB 4
#define CH 16
#define HW 4096
#define KD 144
#define TM 128
#define TN 128
#define KC 16
#define JSPLIT 8
#define JRANGE (HW / JSPLIT)     // 512
#define JTILES (JRANGE / TN)     // 4
#define NCHUNK (KD / KC)         // 9
#define TCHUNK (JTILES * NCHUNK) // 36

// Scratch (__device__ globals: allocation-free)
__device__ float g_QdDup[(size_t)NB * KD * 2 * HW]; // [b][k][2*pix] dup pairs
__device__ float g_Pd[(size_t)NB * KD * HW];        // [b][k][pix]
__device__ float g_qn[NB * HW];
__device__ float g_pn[NB * HW];
__device__ float g_part_d[JSPLIT * NB * HW];
__device__ int   g_part_j[JSPLIT * NB * HW];

__device__ __forceinline__ unsigned long long ffma2(unsigned long long a,
                                                    unsigned long long b,
                                                    unsigned long long c) {
    asm("fma.rn.f32x2 %0, %1, %2, %0;" : "+l"(c) : "l"(a), "l"(b));
    return c;
}

#define CPA16(dst, src) \
    asm volatile("cp.async.cg.shared.global [%0], [%1], 16;\n" ::"r"(dst), "l"(src))

// ---------------------------------------------------------------------------
// Prep: patch descriptors (replicate-pad shifts) + squared norms.
// y==0: s -> duplicated Q layout; y==1: t -> plain P layout.
// ---------------------------------------------------------------------------
__global__ void prep_kernel(const float* __restrict__ s, const float* __restrict__ t) {
    int idx = blockIdx.x * blockDim.x + threadIdx.x;
    if (idx >= NB * HW) return;
    bool isP = blockIdx.y != 0;
    const float* src = isP ? t : s;

    int b = idx >> 12;
    int pix = idx & (HW - 1);
    int iy = pix >> 6, ix = pix & 63;

    float acc = 0.f;
    for (int c = 0; c < CH; c++) {
        const float* sc = src + ((size_t)(b * CH + c) << 12);
#pragma unroll
        for (int dy = 0; dy < 3; dy++) {
            int y = iy + dy - 1; y = y < 0 ? 0 : (y > 63 ? 63 : y);
#pragma unroll
            for (int dx = 0; dx < 3; dx++) {
                int x = ix + dx - 1; x = x < 0 ? 0 : (x > 63 ? 63 : x);
                float v = sc[(y << 6) + x];
                int kidx = c * 9 + dy * 3 + dx;
                if (isP) {
                    g_Pd[(size_t)(b * KD + kidx) * HW + pix] = v;
                } else {
                    float2 vv; vv.x = v; vv.y = v;
                    *reinterpret_cast<float2*>(
                        g_QdDup + (size_t)(b * KD + kidx) * 2 * HW + 2 * pix) = vv;
                }
                acc = fmaf(v, v, acc);
            }
        }
    }
    (isP ? g_pn : g_qn)[idx] = acc;
}

// ---------------------------------------------------------------------------
// Fused GEMM (FFMA2) + partial argmin over a 512-target slice.
// Grid (32, 8, 4) = (qtile, jsplit, batch). 256 threads, 8x8 microtile.
// ---------------------------------------------------------------------------
__global__ __launch_bounds__(256, 1) void nn_kernel() {
    extern __shared__ float sm[];
    float* Qs = sm;                  // [2][KC][256] dup-pair layout
    float* Ps = sm + 2 * KC * 256;   // [2][KC][128]

    const int b = blockIdx.z;
    const int js = blockIdx.y;
    const int q0 = blockIdx.x * TM;
    const int jbase = js * JRANGE;
    const int tid = threadIdx.x;
    const int tx = tid & 15;
    const int ty = tid >> 4;

    const float* Qg = g_QdDup + (size_t)b * KD * 2 * HW + 2 * q0;
    const float* Pg = g_Pd + (size_t)b * KD * HW + jbase;

    const unsigned qs_base = (unsigned)__cvta_generic_to_shared(Qs);
    const unsigned ps_base = (unsigned)__cvta_generic_to_shared(Ps);

    // qn for this thread's 8 rows
    float4 qA = *reinterpret_cast<const float4*>(g_qn + b * HW + q0 + 4 * ty);
    float4 qB = *reinterpret_cast<const float4*>(g_qn + b * HW + q0 + 64 + 4 * ty);
    float qnv[8] = {qA.x, qA.y, qA.z, qA.w, qB.x, qB.y, qB.z, qB.w};

    float bestd[8];
    int   bestj[8];
#pragma unroll
    for (int m = 0; m < 8; m++) { bestd[m] = 3.4e38f; bestj[m] = 0; }

    // ---- async chunk issue ----
    auto issue = [&](int c) {
        if (c < TCHUNK) {
            int jt = c / NCHUNK, kc = c - jt * NCHUNK;
            int buf = c & 1;
            unsigned qd = qs_base + buf * (KC * 256 * 4);
            unsigned pd = ps_base + buf * (KC * 128 * 4);
#pragma unroll
            for (int i = 0; i < 4; i++) {           // Q: 16KB
                int u = tid + i * 256;              // 16B units, 64/row
                const float* src = Qg + (size_t)(kc * KC + (u >> 6)) * (2 * HW) + (u & 63) * 4;
                CPA16(qd + u * 16, src);
            }
#pragma unroll
            for (int i = 0; i < 2; i++) {           // P: 8KB
                int u = tid + i * 256;              // 32/row
                const float* src = Pg + (size_t)(kc * KC + (u >> 5)) * HW + jt * TN + (u & 31) * 4;
                CPA16(pd + u * 16, src);
            }
        }
        asm volatile("cp.async.commit_group;\n");
    };

    issue(0);
    int c = 0;

    for (int jt = 0; jt < JTILES; jt++) {
        unsigned long long acc[8][4];
#pragma unroll
        for (int m = 0; m < 8; m++)
#pragma unroll
            for (int np = 0; np < 4; np++) acc[m][np] = 0ull;

        for (int kc = 0; kc < NCHUNK; kc++) {
            issue(c + 1);
            if (c + 1 < TCHUNK) {
                asm volatile("cp.async.wait_group 1;\n");
            } else {
                asm volatile("cp.async.wait_group 0;\n");
            }
            __syncthreads();

            const float* qb = Qs + (c & 1) * (KC * 256);
            const float* pb = Ps + (c & 1) * (KC * 128);
#pragma unroll
            for (int k = 0; k < KC; k++) {
                ulonglong2 a01 = *reinterpret_cast<const ulonglong2*>(qb + k * 256 + 8 * ty);
                ulonglong2 a23 = *reinterpret_cast<const ulonglong2*>(qb + k * 256 + 8 * ty + 4);
                ulonglong2 a45 = *reinterpret_cast<const ulonglong2*>(qb + k * 256 + 128 + 8 * ty);
                ulonglong2 a67 = *reinterpret_cast<const ulonglong2*>(qb + k * 256 + 128 + 8 * ty + 4);
                ulonglong2 b01 = *reinterpret_cast<const ulonglong2*>(pb + k * 128 + 4 * tx);
                ulonglong2 b23 = *reinterpret_cast<const ulonglong2*>(pb + k * 128 + 64 + 4 * tx);
                unsigned long long ap[8] = {a01.x, a01.y, a23.x, a23.y,
                                            a45.x, a45.y, a67.x, a67.y};
                unsigned long long bp[4] = {b01.x, b01.y, b23.x, b23.y};
#pragma unroll
                for (int m = 0; m < 8; m++)
#pragma unroll
                    for (int np = 0; np < 4; np++)
                        acc[m][np] = ffma2(ap[m], bp[np], acc[m][np]);
            }
            __syncthreads();
            c++;
        }

        // Epilogue: d2 = qn - 2*cross + pn, running min (ascending j, strict <)
        float4 pA = *reinterpret_cast<const float4*>(g_pn + b * HW + jbase + jt * TN + 4 * tx);
        float4 pB = *reinterpret_cast<const float4*>(g_pn + b * HW + jbase + jt * TN + 64 + 4 * tx);
        float pnv[8] = {pA.x, pA.y, pA.z, pA.w, pB.x, pB.y, pB.z, pB.w};
        int jt0 = jbase + jt * TN;
#pragma unroll
        for (int m = 0; m < 8; m++) {
            float qv = qnv[m];
#pragma unroll
            for (int np = 0; np < 4; np++) {
                float fx = __uint_as_float((unsigned)(acc[m][np] & 0xffffffffull));
                float fy = __uint_as_float((unsigned)(acc[m][np] >> 32));
                int n0 = jt0 + ((np & 2) ? 64 : 0) + 4 * tx + 2 * (np & 1);
                float d0 = fmaf(-2.f, fx, qv) + pnv[np * 2];
                float d1 = fmaf(-2.f, fy, qv) + pnv[np * 2 + 1];
                if (d0 < bestd[m]) { bestd[m] = d0; bestj[m] = n0; }
                if (d1 < bestd[m]) { bestd[m] = d1; bestj[m] = n0 + 1; }
            }
        }
    }

    // ---- block reduction across the 16 tx groups ----
    __syncthreads();
    float* rd = sm;                       // [128][17] padded
    int*   rj = (int*)(sm + 128 * 17);
#pragma unroll
    for (int m = 0; m < 8; m++) {
        int row = ((m < 4) ? (4 * ty + m) : (64 + 4 * ty + m - 4));
        rd[row * 17 + tx] = bestd[m];
        rj[row * 17 + tx] = bestj[m];
    }
    __syncthreads();

    if (tid < TM) {
        float bd = rd[tid * 17];
        int   bj = rj[tid * 17];
#pragma unroll
        for (int x = 1; x < 16; x++) {
            float d = rd[tid * 17 + x];
            int   j = rj[tid * 17 + x];
            if (d < bd || (d == bd && j < bj)) { bd = d; bj = j; }
        }
        g_part_d[(size_t)(js * NB + b) * HW + q0 + tid] = bd;
        g_part_j[(size_t)(js * NB + b) * HW + q0 + tid] = bj;
    }
}

// ---------------------------------------------------------------------------
// Merge JSPLIT partials (ascending js => ascending j; strict < keeps first)
// ---------------------------------------------------------------------------
__global__ void reduce_kernel(float* __restrict__ out) {
    int idx = blockIdx.x * blockDim.x + threadIdx.x;
    if (idx >= NB * HW) return;
    int b = idx >> 12, q = idx & (HW - 1);
    float bd = 3.4e38f; int bj = 0;
#pragma unroll
    for (int js = 0; js < JSPLIT; js++) {
        float d = g_part_d[(size_t)(js * NB + b) * HW + q];
        int   j = g_part_j[(size_t)(js * NB + b) * HW + q];
        if (d < bd) { bd = d; bj = j; }
    }
    out[(size_t)b * 2 * HW + q]               = (float)(bj >> 6);
    out[(size_t)b * 2 * HW + HW + q]          = (float)(bj & 63);
    out[(size_t)NB * 2 * HW + (size_t)b * HW + q] = bd;
}

extern "C" void kernel_launch(void* const* d_in, const int* in_sizes, int n_in,
                              void* d_out, int out_size) {
    const float* s = (const float*)d_in[0];
    const float* t = (const float*)d_in[1];
    float* out = (float*)d_out;

    const int smem_bytes = (2 * KC * 256 + 2 * KC * 128) * 4; // 49152
    cudaFuncSetAttribute(nn_kernel, cudaFuncAttributeMaxDynamicSharedMemorySize,
                         smem_bytes);

    prep_kernel<<<dim3((NB * HW + 255) / 256, 2), 256>>>(s, t);
    nn_kernel<<<dim3(HW / TM, JSPLIT, NB), 256, smem_bytes>>>();
    reduce_kernel<<<(NB * HW + 255) / 256, 256>>>(out);
}